// round 1
// baseline (speedup 1.0000x reference)
#include <cuda_runtime.h>
#include <math.h>

// Problem constants (fixed by the reference)
#define N_NODES 50000
#define N_EDGES 800000
#define IN_DIM  128
#define H_DIM   128
#define OUT_DIM 64
#define H1_DIM  512
#define EW_BLOCKS ((N_EDGES * 16 + 255) / 256)   // 50000

// alpha = 0.0 in reference -> x0/conv_w2 terms vanish.
#define BETA0 0.6931471805599453f   /* ln(2)   */
#define BETA1 0.4054651081081644f   /* ln(1.5) */

// ---------------- device scratch (static globals; no cudaMalloc allowed) ----
__device__ float  g_h1[N_NODES * H1_DIM];
__device__ float  g_h2[N_NODES * OUT_DIM];
__device__ float  g_logits[N_NODES * OUT_DIM];
__device__ float  g_lp[N_NODES * OUT_DIM];
__device__ float  g_P[OUT_DIM * OUT_DIM];
__device__ float  g_hA[N_NODES * H_DIM];
__device__ float  g_hB[N_NODES * H_DIM];
__device__ float  g_agg[N_NODES * H_DIM];
__device__ float  g_ewraw[N_EDGES];
__device__ float  g_ewp[N_EDGES];     // per-CSR-slot weight (raw, then normalized in place)
__device__ float  g_normw[N_EDGES];
__device__ int    g_esrc[N_EDGES];
__device__ int    g_cnt[N_NODES];
__device__ int    g_cursor[N_NODES];
__device__ int    g_rowptr[N_NODES + 1];
__device__ double g_psum[EW_BLOCKS];
__device__ double g_psum2[EW_BLOCKS];
__device__ float  g_stats[2];         // mean, scale = sqrt(1e-4/var)
__device__ float  g_dinv[N_NODES];

// ---------------- generic fp32 tiled GEMM: C = relu?( alpha*(A@B) + bias + addA*A ) ----
// BM=128, BN=64, BK=16, 256 threads, 8x4 per thread.
#define BM 128
#define BN 64
#define BK 16
#define TM 8
#define TN 4

__global__ void gemm_kernel(const float* __restrict__ A, const float* __restrict__ B,
                            const float* __restrict__ bias, float* __restrict__ C,
                            int M, int N, int K, float alpha, float addA, int do_relu)
{
    __shared__ float As[BK][BM];
    __shared__ float Bs[BK][BN];
    const int tid = threadIdx.x;             // 0..255
    const int tx = tid & 15;                 // 0..15
    const int ty = tid >> 4;                 // 0..15
    const int m0 = blockIdx.x * BM;
    const int n0 = blockIdx.y * BN;

    float acc[TM][TN];
#pragma unroll
    for (int i = 0; i < TM; i++)
#pragma unroll
        for (int j = 0; j < TN; j++) acc[i][j] = 0.f;

    for (int k0 = 0; k0 < K; k0 += BK) {
        // A tile: 128x16, 8 elems/thread. consecutive tid -> consecutive k.
#pragma unroll
        for (int i = 0; i < 8; i++) {
            int k = tid & 15;
            int m = (tid >> 4) + i * 16;
            int gm = m0 + m;
            float v = 0.f;
            if (gm < M) v = A[(size_t)gm * K + (k0 + k)];
            As[k][m] = v;
        }
        // B tile: 16x64, 4 elems/thread (N is always a multiple of 64 here).
#pragma unroll
        for (int i = 0; i < 4; i++) {
            int n = tid & 63;
            int k = (tid >> 6) + i * 4;
            Bs[k][n] = B[(size_t)(k0 + k) * N + (n0 + n)];
        }
        __syncthreads();
#pragma unroll
        for (int kk = 0; kk < BK; kk++) {
            float a[TM], b[TN];
            float4 t0 = *(const float4*)&As[kk][ty * TM];
            float4 t1 = *(const float4*)&As[kk][ty * TM + 4];
            a[0]=t0.x; a[1]=t0.y; a[2]=t0.z; a[3]=t0.w;
            a[4]=t1.x; a[5]=t1.y; a[6]=t1.z; a[7]=t1.w;
            float4 u0 = *(const float4*)&Bs[kk][tx * TN];
            b[0]=u0.x; b[1]=u0.y; b[2]=u0.z; b[3]=u0.w;
#pragma unroll
            for (int i = 0; i < TM; i++)
#pragma unroll
                for (int j = 0; j < TN; j++)
                    acc[i][j] += a[i] * b[j];
        }
        __syncthreads();
    }
    // epilogue
#pragma unroll
    for (int i = 0; i < TM; i++) {
        int gm = m0 + ty * TM + i;
        if (gm >= M) continue;
#pragma unroll
        for (int j = 0; j < TN; j++) {
            int gn = n0 + tx * TN + j;
            float v = alpha * acc[i][j];
            if (bias) v += bias[gn];
            if (addA != 0.f) v += addA * A[(size_t)gm * K + gn];  // only used when N==K
            if (do_relu) v = fmaxf(v, 0.f);
            C[(size_t)gm * N + gn] = v;
        }
    }
}

// ---------------- P = relu(SCALE * parsing[0]) ----------------
__global__ void p_kernel(const float* __restrict__ parsing)
{
    int i = blockIdx.x * blockDim.x + threadIdx.x;
    if (i < OUT_DIM * OUT_DIM) g_P[i] = fmaxf(2.0f * parsing[i], 0.0f);
}

// ---------------- edge weights: ew[e] = dot(logits[row[e]], lp[col[e]]) ------
// 16 lanes per edge; block-level double partial sums for mean/var.
__global__ void ew_kernel(const float* __restrict__ logits, const float* __restrict__ lp,
                          const int* __restrict__ erow, const int* __restrict__ ecol)
{
    int t = blockIdx.x * 256 + threadIdx.x;
    int e = t >> 4;
    int l = t & 15;
    float v = 0.f;
    if (e < N_EDGES) {
        int r = erow[e], c = ecol[e];
        float4 a = *(const float4*)(logits + (size_t)r * OUT_DIM + l * 4);
        float4 b = *(const float4*)(lp + (size_t)c * OUT_DIM + l * 4);
        v = a.x * b.x + a.y * b.y + a.z * b.z + a.w * b.w;
    }
#pragma unroll
    for (int off = 8; off > 0; off >>= 1)
        v += __shfl_xor_sync(0xffffffffu, v, off);
    if (l == 0 && e < N_EDGES) g_ewraw[e] = v;

    double s  = (l == 0 && e < N_EDGES) ? (double)v : 0.0;
    double s2 = (l == 0 && e < N_EDGES) ? (double)v * (double)v : 0.0;
    __shared__ double sh1[256];
    __shared__ double sh2[256];
    sh1[threadIdx.x] = s; sh2[threadIdx.x] = s2;
    __syncthreads();
    for (int off = 128; off > 0; off >>= 1) {
        if (threadIdx.x < off) {
            sh1[threadIdx.x] += sh1[threadIdx.x + off];
            sh2[threadIdx.x] += sh2[threadIdx.x + off];
        }
        __syncthreads();
    }
    if (threadIdx.x == 0) { g_psum[blockIdx.x] = sh1[0]; g_psum2[blockIdx.x] = sh2[0]; }
}

__global__ void stats_kernel()
{
    int t = threadIdx.x;
    double s = 0.0, s2 = 0.0;
    for (int i = t; i < EW_BLOCKS; i += 1024) { s += g_psum[i]; s2 += g_psum2[i]; }
    __shared__ double sh1[1024];
    __shared__ double sh2[1024];
    sh1[t] = s; sh2[t] = s2;
    __syncthreads();
    for (int off = 512; off > 0; off >>= 1) {
        if (t < off) { sh1[t] += sh1[t + off]; sh2[t] += sh2[t + off]; }
        __syncthreads();
    }
    if (t == 0) {
        double sum = sh1[0], sumsq = sh2[0];
        double mean = sum / (double)N_EDGES;
        double var = (sumsq - sum * sum / (double)N_EDGES) / (double)(N_EDGES - 1);
        g_stats[0] = (float)mean;
        g_stats[1] = (float)sqrt(1e-4 / var);
    }
}

// ---------------- CSR build (sorted by destination col) ----------------------
__global__ void count_kernel(const int* __restrict__ ecol)
{
    int e = blockIdx.x * blockDim.x + threadIdx.x;
    if (e < N_EDGES) atomicAdd(&g_cnt[ecol[e]], 1);
}

__global__ void scan_kernel()
{
    __shared__ int sh[1024];
    __shared__ int s_carry;
    int t = threadIdx.x;
    if (t == 0) { s_carry = 0; g_rowptr[0] = 0; }
    __syncthreads();
    for (int base = 0; base < N_NODES; base += 1024) {
        int v = (base + t < N_NODES) ? g_cnt[base + t] : 0;
        sh[t] = v;
        __syncthreads();
        for (int off = 1; off < 1024; off <<= 1) {
            int add = (t >= off) ? sh[t - off] : 0;
            __syncthreads();
            sh[t] += add;
            __syncthreads();
        }
        int inc = sh[t] + s_carry;          // inclusive sum incl. carry
        if (base + t < N_NODES) {
            g_rowptr[base + t + 1] = inc;
            g_cursor[base + t] = inc - v;   // exclusive
        }
        int total = sh[1023];
        __syncthreads();                    // all reads of s_carry/sh done
        if (t == 0) s_carry += total;
        __syncthreads();
    }
}

__global__ void scatter_kernel(const int* __restrict__ erow, const int* __restrict__ ecol)
{
    int e = blockIdx.x * blockDim.x + threadIdx.x;
    if (e < N_EDGES) {
        int p = atomicAdd(&g_cursor[ecol[e]], 1);
        g_esrc[p] = erow[e];
        g_ewp[p] = g_ewraw[e];
    }
}

// normalize ew in place (CSR order), compute deg (incl. self-loop w=1) and dinv
__global__ void deg_kernel()
{
    int warp = (blockIdx.x * blockDim.x + threadIdx.x) >> 5;
    int lane = threadIdx.x & 31;
    if (warp >= N_NODES) return;
    float mean = g_stats[0], scale = g_stats[1];
    int s0 = g_rowptr[warp], s1 = g_rowptr[warp + 1];
    float s = 0.f;
    for (int p = s0 + lane; p < s1; p += 32) {
        float w = (g_ewp[p] - mean) * scale + 1.0f;
        g_ewp[p] = w;
        s += w;
    }
#pragma unroll
    for (int off = 16; off > 0; off >>= 1)
        s += __shfl_xor_sync(0xffffffffu, s, off);
    if (lane == 0) {
        float deg = s + 1.0f;  // self loop weight 1
        g_dinv[warp] = (deg > 0.f) ? rsqrtf(deg) : 0.f;
    }
}

__global__ void normw_kernel()
{
    int warp = (blockIdx.x * blockDim.x + threadIdx.x) >> 5;
    int lane = threadIdx.x & 31;
    if (warp >= N_NODES) return;
    float di = g_dinv[warp];
    int s0 = g_rowptr[warp], s1 = g_rowptr[warp + 1];
    for (int p = s0 + lane; p < s1; p += 32)
        g_normw[p] = g_dinv[g_esrc[p]] * g_ewp[p] * di;
}

// ---------------- SpMM: agg[n] = sum_in normw*h[src] + dinv[n]^2 * h[n] ------
__global__ void spmm_kernel(const float* __restrict__ hin, float* __restrict__ agg)
{
    int warp = (blockIdx.x * blockDim.x + threadIdx.x) >> 5;
    int lane = threadIdx.x & 31;
    if (warp >= N_NODES) return;
    const float4* h4 = (const float4*)hin;
    float di = g_dinv[warp];
    float selfw = di * di;
    float4 hv = h4[(size_t)warp * 32 + lane];
    float4 acc;
    acc.x = selfw * hv.x; acc.y = selfw * hv.y; acc.z = selfw * hv.z; acc.w = selfw * hv.w;
    int s0 = g_rowptr[warp], s1 = g_rowptr[warp + 1];
    for (int p = s0; p < s1; p++) {
        float w = g_normw[p];
        int src = g_esrc[p];
        float4 v = h4[(size_t)src * 32 + lane];
        acc.x += w * v.x; acc.y += w * v.y; acc.z += w * v.z; acc.w += w * v.w;
    }
    ((float4*)agg)[(size_t)warp * 32 + lane] = acc;
}

// ---------------- launch ----------------------------------------------------
extern "C" void kernel_launch(void* const* d_in, const int* in_sizes, int n_in,
                              void* d_out, int out_size)
{
    const float* x       = (const float*)d_in[0];
    const int*   eidx    = (const int*)d_in[1];
    const float* w1      = (const float*)d_in[2];
    const float* b1      = (const float*)d_in[3];
    const float* w2      = (const float*)d_in[4];
    const float* b2      = (const float*)d_in[5];
    const float* w3      = (const float*)d_in[6];
    const float* b3      = (const float*)d_in[7];
    const float* parsing = (const float*)d_in[8];
    const float* l0w     = (const float*)d_in[9];
    const float* l0b     = (const float*)d_in[10];
    const float* l1w     = (const float*)d_in[11];
    const float* l1b     = (const float*)d_in[12];
    const float* cw1     = (const float*)d_in[13];
    float* out = (float*)d_out;
    const int* erow = eidx;
    const int* ecol = eidx + N_EDGES;

    float *p_h1, *p_h2, *p_logits, *p_lp, *p_P, *p_hA, *p_hB, *p_agg;
    int *p_cnt;
    cudaGetSymbolAddress((void**)&p_h1, g_h1);
    cudaGetSymbolAddress((void**)&p_h2, g_h2);
    cudaGetSymbolAddress((void**)&p_logits, g_logits);
    cudaGetSymbolAddress((void**)&p_lp, g_lp);
    cudaGetSymbolAddress((void**)&p_P, g_P);
    cudaGetSymbolAddress((void**)&p_hA, g_hA);
    cudaGetSymbolAddress((void**)&p_hB, g_hB);
    cudaGetSymbolAddress((void**)&p_agg, g_agg);
    cudaGetSymbolAddress((void**)&p_cnt, g_cnt);

    const int gmx = (N_NODES + BM - 1) / BM;  // 391

    // P = relu(2*parsing[0])
    p_kernel<<<4, 1024>>>(parsing);
    // MLP
    gemm_kernel<<<dim3(gmx, 512 / BN), 256>>>(x, w1, b1, p_h1, N_NODES, 512, IN_DIM, 1.f, 0.f, 1);
    gemm_kernel<<<dim3(gmx, 1), 256>>>(p_h1, w2, b2, p_h2, N_NODES, OUT_DIM, H1_DIM, 1.f, 0.f, 1);
    gemm_kernel<<<dim3(gmx, 1), 256>>>(p_h2, w3, b3, p_logits, N_NODES, OUT_DIM, OUT_DIM, 1.f, 0.f, 0);
    gemm_kernel<<<dim3(gmx, 1), 256>>>(p_logits, p_P, nullptr, p_lp, N_NODES, OUT_DIM, OUT_DIM, 1.f, 0.f, 0);
    // x0 = relu(x @ lin0 + b) -> initial hcur
    gemm_kernel<<<dim3(gmx, 2), 256>>>(x, l0w, l0b, p_hA, N_NODES, H_DIM, IN_DIM, 1.f, 0.f, 1);
    // edge weights + stats
    ew_kernel<<<EW_BLOCKS, 256>>>(p_logits, p_lp, erow, ecol);
    stats_kernel<<<1, 1024>>>();
    // CSR build
    cudaMemsetAsync(p_cnt, 0, N_NODES * sizeof(int));
    count_kernel<<<(N_EDGES + 255) / 256, 256>>>(ecol);
    scan_kernel<<<1, 1024>>>();
    scatter_kernel<<<(N_EDGES + 255) / 256, 256>>>(erow, ecol);
    deg_kernel<<<(N_NODES + 7) / 8, 256>>>();
    normw_kernel<<<(N_NODES + 7) / 8, 256>>>();
    // layer 0
    spmm_kernel<<<(N_NODES + 7) / 8, 256>>>(p_hA, p_agg);
    gemm_kernel<<<dim3(gmx, 2), 256>>>(p_agg, cw1, nullptr, p_hB,
                                       N_NODES, H_DIM, H_DIM, BETA0, 1.f - BETA0, 1);
    // layer 1
    spmm_kernel<<<(N_NODES + 7) / 8, 256>>>(p_hB, p_agg);
    gemm_kernel<<<dim3(gmx, 2), 256>>>(p_agg, cw1 + H_DIM * H_DIM, nullptr, p_hA,
                                       N_NODES, H_DIM, H_DIM, BETA1, 1.f - BETA1, 1);
    // output
    gemm_kernel<<<dim3(gmx, 1), 256>>>(p_hA, l1w, l1b, out, N_NODES, OUT_DIM, H_DIM, 1.f, 0.f, 0);
}